// round 1
// baseline (speedup 1.0000x reference)
#include <cuda_runtime.h>

#define Bsz 16
#define Lseq 576
#define Hh 12
#define Dh 64
#define Mf 8
#define ROWS (Bsz*Lseq*Hh)   // 110592

// Scratch (device globals: allocation-free rule)
__device__ float g_qp[Bsz*Hh*Lseq*Mf];     // [B][H][L][M]
__device__ float g_kp[Bsz*Hh*Lseq*Mf];     // [B][H][L][M]
__device__ float g_colsum[Hh*Lseq];        // [H][L]
__device__ float g_kssum[Bsz*Hh*Mf];       // [B][H][M]

// ---------------------------------------------------------------------------
// Kernel 1: q' / k' = relu(ratio * x @ projT) + 1e-3, written [B][H][L][M]
// grid (ROWS/32, 2), block 256. 32 rows staged in smem, 8 outputs/row.
// ---------------------------------------------------------------------------
__global__ void featurize_kernel(const float* __restrict__ q,
                                 const float* __restrict__ k,
                                 const float* __restrict__ proj) {
    const float* x = (blockIdx.y == 0) ? q : k;
    float* outp    = (blockIdx.y == 0) ? g_qp : g_kp;

    __shared__ __align__(16) float sX[32][68];   // 68: pad, 272B row (16B-mult)
    __shared__ __align__(16) float sP[8][68];

    int t = threadIdx.x;
    for (int idx = t; idx < Mf*Dh; idx += 256)
        sP[idx >> 6][idx & 63] = proj[idx];

    int row0 = blockIdx.x * 32;
    for (int idx = t; idx < 32*Dh; idx += 256)
        sX[idx >> 6][idx & 63] = x[(size_t)row0 * Dh + idx];
    __syncthreads();

    int r = t >> 3, m = t & 7;
    const float4* xr = (const float4*)&sX[r][0];
    const float4* pr = (const float4*)&sP[m][0];
    float acc = 0.f;
#pragma unroll
    for (int dd = 0; dd < Dh/4; dd++) {
        float4 xv = xr[dd], pv = pr[dd];
        acc += xv.x*pv.x + xv.y*pv.y + xv.z*pv.z + xv.w*pv.w;
    }
    const float ratio = 0.35355339059327373f;   // 1/sqrt(8)
    float res = fmaxf(acc * ratio, 0.f) + 1e-3f;

    int row = row0 + r;                 // row = (b*L + l)*H + h
    int h  = row % Hh;
    int bl = row / Hh;
    int l  = bl % Lseq;
    int b  = bl / Lseq;
    outp[(((size_t)(b*Hh + h))*Lseq + l)*Mf + m] = res;
}

// ---------------------------------------------------------------------------
// Kernel 2a/2b: colsum[h][j] = sum_i mask[h][i][j]
// ---------------------------------------------------------------------------
__global__ void colsum_init_kernel() {
    int i = blockIdx.x * 256 + threadIdx.x;
    if (i < Hh*Lseq) g_colsum[i] = 0.f;
}

__global__ void colsum_kernel(const float* __restrict__ mask) {
    int h = blockIdx.x;
    int chunk = blockIdx.y;          // 4 chunks of 144 i-rows
    int j = threadIdx.x;             // 576 threads, coalesced over j
    int i0 = chunk * 144;
    const float* mcol = mask + ((size_t)h*Lseq + i0)*Lseq + j;
    float acc = 0.f;
    for (int i = 0; i < 144; i++) acc += mcol[(size_t)i * Lseq];
    atomicAdd(&g_colsum[h*Lseq + j], acc);
}

// ---------------------------------------------------------------------------
// Kernel 3: ks_sum[b][h][m] = sum_j colsum[h][j] * k'[b][h][j][m]
// grid (B, H), block 256
// ---------------------------------------------------------------------------
__global__ void kssum_kernel() {
    int b = blockIdx.x, h = blockIdx.y;
    int t = threadIdx.x, m = t & 7, g = t >> 3;   // 32 j-groups x 8 m
    const float* kp = g_kp + ((size_t)(b*Hh + h))*Lseq*Mf;
    const float* cs = g_colsum + h*Lseq;
    float acc = 0.f;
    for (int j = g; j < Lseq; j += 32) acc += cs[j] * kp[j*Mf + m];
    __shared__ float red[32][8];
    red[g][m] = acc;
    __syncthreads();
    for (int off = 16; off >= 1; off >>= 1) {
        if (g < off) red[g][m] += red[g+off][m];
        __syncthreads();
    }
    if (t < 8) g_kssum[(b*Hh + h)*Mf + t] = red[0][t];
}

// ---------------------------------------------------------------------------
// Kernel 4 (main): per (b, h, i-tile of 64):
//   loop j-tiles: A = mask ⊙ (Q' K'^T) in smem;  C += A @ V  (4x4 microtiles)
//   epilogue: out = C / (q' . ks_sum)
// ---------------------------------------------------------------------------
__global__ __launch_bounds__(256, 2)
void attn_main_kernel(const float* __restrict__ v,
                      const float* __restrict__ mask,
                      float* __restrict__ out) {
    int b = blockIdx.z, h = blockIdx.y;
    int i0 = blockIdx.x * 64;
    int t = threadIdx.x;

    __shared__ __align__(16) float sQ[8][64];    // q' m-major
    __shared__ __align__(16) float sK[8][64];    // k' m-major
    __shared__ __align__(16) float sA[64][64];   // masked scores tile
    __shared__ __align__(16) float sV[64][64];   // V tile [kk][d]
    __shared__ float sKS[8];

    const float* qp  = g_qp + (((size_t)(b*Hh + h))*Lseq + i0)*Mf;
    const float* kpb = g_kp + ((size_t)(b*Hh + h))*Lseq*Mf;

    for (int idx = t; idx < 512; idx += 256) sQ[idx & 7][idx >> 3] = qp[idx];
    if (t < 8) sKS[t] = g_kssum[(b*Hh + h)*Mf + t];

    int tx = t & 63, ty = t >> 6;     // phase A: 64 j-cols x 4 i-groups
    int tc = t & 15, tr = t >> 4;     // phase B: 16x16 thread grid, 4x4 micro

    float c[4][4];
#pragma unroll
    for (int u = 0; u < 4; u++)
#pragma unroll
        for (int w = 0; w < 4; w++) c[u][w] = 0.f;

    for (int j0 = 0; j0 < Lseq; j0 += 64) {
        __syncthreads();   // protect prior iteration's sA/sV reads (and sQ on iter 0)

        // load k' tile (m-major)
        for (int idx = t; idx < 512; idx += 256)
            sK[idx & 7][idx >> 3] = kpb[j0*Mf + idx];

        // load V tile: [64][64], coalesced float4
        {
            int kk = t >> 4, d4 = t & 15;
#pragma unroll
            for (int rr = 0; rr < 4; rr++) {
                int krow = kk + rr*16;
                *(float4*)&sV[krow][d4*4] =
                    *(const float4*)&v[(((size_t)(b*Lseq + j0 + krow))*Hh + h)*Dh + d4*4];
            }
        }
        __syncthreads();

        // phase A: sA[i][j] = mask[h,i0+i,j0+j] * sum_m q'[i,m] k'[j,m]
        const float* mrow = mask + ((size_t)h*Lseq + i0)*Lseq + j0 + tx;
#pragma unroll
        for (int r = 0; r < 16; r++) {
            int i = (r << 2) + ty;
            float s = 0.f;
#pragma unroll
            for (int m = 0; m < 8; m++) s += sQ[m][i] * sK[m][tx];
            sA[i][tx] = s * mrow[(size_t)i * Lseq];
        }
        __syncthreads();

        // phase B: C += A @ V, kk unrolled by 4, all float4 smem traffic
#pragma unroll 4
        for (int kk4 = 0; kk4 < 16; kk4++) {
            float4 a0 = *(const float4*)&sA[tr*4 + 0][kk4*4];
            float4 a1 = *(const float4*)&sA[tr*4 + 1][kk4*4];
            float4 a2 = *(const float4*)&sA[tr*4 + 2][kk4*4];
            float4 a3 = *(const float4*)&sA[tr*4 + 3][kk4*4];
            float4 b0 = *(const float4*)&sV[kk4*4 + 0][tc*4];
            float4 b1 = *(const float4*)&sV[kk4*4 + 1][tc*4];
            float4 b2 = *(const float4*)&sV[kk4*4 + 2][tc*4];
            float4 b3 = *(const float4*)&sV[kk4*4 + 3][tc*4];

            c[0][0] += a0.x*b0.x + a0.y*b1.x + a0.z*b2.x + a0.w*b3.x;
            c[0][1] += a0.x*b0.y + a0.y*b1.y + a0.z*b2.y + a0.w*b3.y;
            c[0][2] += a0.x*b0.z + a0.y*b1.z + a0.z*b2.z + a0.w*b3.z;
            c[0][3] += a0.x*b0.w + a0.y*b1.w + a0.z*b2.w + a0.w*b3.w;

            c[1][0] += a1.x*b0.x + a1.y*b1.x + a1.z*b2.x + a1.w*b3.x;
            c[1][1] += a1.x*b0.y + a1.y*b1.y + a1.z*b2.y + a1.w*b3.y;
            c[1][2] += a1.x*b0.z + a1.y*b1.z + a1.z*b2.z + a1.w*b3.z;
            c[1][3] += a1.x*b0.w + a1.y*b1.w + a1.z*b2.w + a1.w*b3.w;

            c[2][0] += a2.x*b0.x + a2.y*b1.x + a2.z*b2.x + a2.w*b3.x;
            c[2][1] += a2.x*b0.y + a2.y*b1.y + a2.z*b2.y + a2.w*b3.y;
            c[2][2] += a2.x*b0.z + a2.y*b1.z + a2.z*b2.z + a2.w*b3.z;
            c[2][3] += a2.x*b0.w + a2.y*b1.w + a2.z*b2.w + a2.w*b3.w;

            c[3][0] += a3.x*b0.x + a3.y*b1.x + a3.z*b2.x + a3.w*b3.x;
            c[3][1] += a3.x*b0.y + a3.y*b1.y + a3.z*b2.y + a3.w*b3.y;
            c[3][2] += a3.x*b0.z + a3.y*b1.z + a3.z*b2.z + a3.w*b3.z;
            c[3][3] += a3.x*b0.w + a3.y*b1.w + a3.z*b2.w + a3.w*b3.w;
        }
    }

    // epilogue: normalizer = q' . ks_sum ; divide and store
#pragma unroll
    for (int u = 0; u < 4; u++) {
        int i = tr*4 + u;
        float s = 0.f;
#pragma unroll
        for (int m = 0; m < 8; m++) s += sQ[m][i] * sKS[m];
        float inv = 1.f / s;
        float4 o = make_float4(c[u][0]*inv, c[u][1]*inv, c[u][2]*inv, c[u][3]*inv);
        *(float4*)&out[(((size_t)(b*Lseq + i0 + i))*Hh + h)*Dh + tc*4] = o;
    }
}

// ---------------------------------------------------------------------------
extern "C" void kernel_launch(void* const* d_in, const int* in_sizes, int n_in,
                              void* d_out, int out_size) {
    const float* q    = (const float*)d_in[0];
    const float* k    = (const float*)d_in[1];
    const float* v    = (const float*)d_in[2];
    const float* proj = (const float*)d_in[3];
    const float* mask = (const float*)d_in[4];
    float* out = (float*)d_out;

    featurize_kernel<<<dim3(ROWS/32, 2), 256>>>(q, k, proj);
    colsum_init_kernel<<<(Hh*Lseq + 255)/256, 256>>>();
    colsum_kernel<<<dim3(Hh, 4), 576>>>(mask);
    kssum_kernel<<<dim3(Bsz, Hh), 256>>>();
    attn_main_kernel<<<dim3(Lseq/64, Hh, Bsz), 256>>>(v, mask, out);
}

// round 4
// speedup vs baseline: 1.5942x; 1.5942x over previous
#include <cuda_runtime.h>

#define Bsz 16
#define Lseq 576
#define Hh 12
#define Dh 64
#define Mf 8
#define ROWS (Bsz*Lseq*Hh)   // 110592

// Scratch (device globals: allocation-free rule)
__device__ float g_qp[Bsz*Hh*Lseq*Mf];     // [B][H][L][M]
__device__ float g_kp[Bsz*Hh*Lseq*Mf];     // [B][H][L][M]
__device__ float g_colsum[Hh*Lseq];        // [H][L]
__device__ float g_kssum[Bsz*Hh*Mf];       // [B][H][M]

__device__ __forceinline__ float to_tf32(float x) {
    float r;
    asm("cvt.rna.tf32.f32 %0, %1;" : "=f"(r) : "f"(x));
    return r;
}

__device__ __forceinline__ void mma_tf32(float c[4],
                                         unsigned a0, unsigned a1, unsigned a2, unsigned a3,
                                         unsigned b0, unsigned b1) {
    asm volatile(
        "mma.sync.aligned.m16n8k8.row.col.f32.tf32.tf32.f32 "
        "{%0,%1,%2,%3}, {%4,%5,%6,%7}, {%8,%9}, {%0,%1,%2,%3};\n"
        : "+f"(c[0]), "+f"(c[1]), "+f"(c[2]), "+f"(c[3])
        : "r"(a0), "r"(a1), "r"(a2), "r"(a3), "r"(b0), "r"(b1));
}

// ---------------------------------------------------------------------------
// Kernel 1: q' / k' = relu(ratio * x @ projT) + 1e-3, written [B][H][L][M]
// ---------------------------------------------------------------------------
__global__ void featurize_kernel(const float* __restrict__ q,
                                 const float* __restrict__ k,
                                 const float* __restrict__ proj) {
    const float* x = (blockIdx.y == 0) ? q : k;
    float* outp    = (blockIdx.y == 0) ? g_qp : g_kp;

    __shared__ __align__(16) float sX[32][68];
    __shared__ __align__(16) float sP[8][68];

    int t = threadIdx.x;
    for (int idx = t; idx < Mf*Dh; idx += 256)
        sP[idx >> 6][idx & 63] = proj[idx];

    int row0 = blockIdx.x * 32;
    for (int idx = t; idx < 32*Dh; idx += 256)
        sX[idx >> 6][idx & 63] = x[(size_t)row0 * Dh + idx];
    __syncthreads();

    int r = t >> 3, m = t & 7;
    const float4* xr = (const float4*)&sX[r][0];
    const float4* pr = (const float4*)&sP[m][0];
    float acc = 0.f;
#pragma unroll
    for (int dd = 0; dd < Dh/4; dd++) {
        float4 xv = xr[dd], pv = pr[dd];
        acc += xv.x*pv.x + xv.y*pv.y + xv.z*pv.z + xv.w*pv.w;
    }
    const float ratio = 0.35355339059327373f;   // 1/sqrt(8)
    float res = fmaxf(acc * ratio, 0.f) + 1e-3f;

    int row = row0 + r;                 // row = (b*L + l)*H + h
    int h  = row % Hh;
    int bl = row / Hh;
    int l  = bl % Lseq;
    int b  = bl / Lseq;
    outp[(((size_t)(b*Hh + h))*Lseq + l)*Mf + m] = res;
}

// ---------------------------------------------------------------------------
// Kernel 2: colsum[h][j] = sum_i mask[h][i][j]
// ---------------------------------------------------------------------------
__global__ void colsum_init_kernel() {
    int i = blockIdx.x * 256 + threadIdx.x;
    if (i < Hh*Lseq) g_colsum[i] = 0.f;
}

__global__ void colsum_kernel(const float* __restrict__ mask) {
    int h = blockIdx.x;
    int chunk = blockIdx.y;          // 4 chunks of 144 i-rows
    int j = threadIdx.x;             // 576 threads, coalesced over j
    int i0 = chunk * 144;
    const float* mcol = mask + ((size_t)h*Lseq + i0)*Lseq + j;
    float acc = 0.f;
    for (int i = 0; i < 144; i++) acc += mcol[(size_t)i * Lseq];
    atomicAdd(&g_colsum[h*Lseq + j], acc);
}

// ---------------------------------------------------------------------------
// Kernel 3: ks_sum[b][h][m] = sum_j colsum[h][j] * k'[b][h][j][m]
// Coalesced 32-wide loads; shfl reduction (lanes 0..7 hold m-partials).
// ---------------------------------------------------------------------------
__global__ void kssum_kernel() {
    int bh = blockIdx.x;             // b*Hh + h
    int h  = bh % Hh;
    int t = threadIdx.x, lane = t & 31, w = t >> 5;   // 8 warps
    const float* kp = g_kp + (size_t)bh * Lseq * Mf;
    const float* cs = g_colsum + h * Lseq;

    float acc = 0.f;
    // 4608 elements, 144 warp-chunks of 32, 18 iterations over 8 warps
    for (int c = w; c < 144; c += 8) {
        int base = c * 32;
        int j = (base + lane) >> 3;          // element index / 8
        acc += kp[base + lane] * cs[j];
    }
    acc += __shfl_down_sync(0xffffffffu, acc, 16);
    acc += __shfl_down_sync(0xffffffffu, acc, 8);

    __shared__ float red[8][8];
    if (lane < 8) red[w][lane] = acc;
    __syncthreads();
    if (t < 8) {
        float s = red[0][t] + red[1][t] + red[2][t] + red[3][t]
                + red[4][t] + red[5][t] + red[6][t] + red[7][t];
        g_kssum[bh * Mf + t] = s;
    }
}

// ---------------------------------------------------------------------------
// Kernel 4 (main): per (b, h, i-tile of 64):
//   phase A (SIMT fp32): sA = mask ⊙ (Q' K'^T), tf32-rounded
//   phase B (mma.sync tf32): C += sA @ sV, warps in 2x4 grid (32i x 16d each)
//   epilogue: out = C / (q' . ks_sum)
// ---------------------------------------------------------------------------
__global__ __launch_bounds__(256, 2)
void attn_main_kernel(const float* __restrict__ v,
                      const float* __restrict__ mask,
                      float* __restrict__ out) {
    int b = blockIdx.z, h = blockIdx.y;
    int i0 = blockIdx.x * 64;
    int t = threadIdx.x;

    __shared__ __align__(16) float sQ[8][64];    // q' m-major
    __shared__ __align__(16) float sK[8][64];    // k' m-major
    __shared__ __align__(16) float sA[64][68];   // masked scores (tf32-rounded); pad 68
    __shared__ __align__(16) float sV[64][72];   // V tile [kk][d]; pad 72
    __shared__ float sKS[8];

    const float* qp  = g_qp + (((size_t)(b*Hh + h))*Lseq + i0)*Mf;
    const float* kpb = g_kp + ((size_t)(b*Hh + h))*Lseq*Mf;

    for (int idx = t; idx < 512; idx += 256) sQ[idx & 7][idx >> 3] = qp[idx];
    if (t < 8) sKS[t] = g_kssum[(b*Hh + h)*Mf + t];

    // phase A mapping
    int tx = t & 63, ty = t >> 6;
    // phase B mapping: 8 warps in 2 (i) x 4 (d) grid
    int lane = t & 31, w = t >> 5;
    int wi = w >> 2, wd = w & 3;
    int gid = lane >> 2, tig = lane & 3;

    float c[2][2][4];
#pragma unroll
    for (int mt = 0; mt < 2; mt++)
#pragma unroll
        for (int nt = 0; nt < 2; nt++)
#pragma unroll
            for (int u = 0; u < 4; u++) c[mt][nt][u] = 0.f;

    for (int j0 = 0; j0 < Lseq; j0 += 64) {
        __syncthreads();   // protect prior iteration's sA/sV reads

        // load k' tile (m-major)
        for (int idx = t; idx < 512; idx += 256)
            sK[idx & 7][idx >> 3] = kpb[j0*Mf + idx];

        // load V tile [64][64] -> sV (tf32-rounded), coalesced float4
        {
            int kk = t >> 4, d4 = t & 15;
#pragma unroll
            for (int rr = 0; rr < 4; rr++) {
                int krow = kk + rr*16;
                float4 vv = *(const float4*)&v[(((size_t)(b*Lseq + j0 + krow))*Hh + h)*Dh + d4*4];
                vv.x = to_tf32(vv.x); vv.y = to_tf32(vv.y);
                vv.z = to_tf32(vv.z); vv.w = to_tf32(vv.w);
                *(float4*)&sV[krow][d4*4] = vv;
            }
        }
        __syncthreads();

        // phase A: sA[i][j] = tf32(mask[h,i0+i,j0+j] * sum_m q'[i,m] k'[j,m])
        const float* mrow = mask + ((size_t)h*Lseq + i0)*Lseq + j0 + tx;
#pragma unroll
        for (int r = 0; r < 16; r++) {
            int i = (r << 2) + ty;
            float s = 0.f;
#pragma unroll
            for (int m = 0; m < 8; m++) s += sQ[m][i] * sK[m][tx];
            sA[i][tx] = to_tf32(s * mrow[(size_t)i * Lseq]);
        }
        __syncthreads();

        // phase B: tf32 mma. Warp computes 32i x 16d; k0 over 64 in steps of 8.
#pragma unroll
        for (int k0 = 0; k0 < 64; k0 += 8) {
            unsigned a[2][4];
#pragma unroll
            for (int mt = 0; mt < 2; mt++) {
                int rl = wi*32 + mt*16 + gid;
                a[mt][0] = __float_as_uint(sA[rl    ][k0 + tig    ]);
                a[mt][1] = __float_as_uint(sA[rl + 8][k0 + tig    ]);
                a[mt][2] = __float_as_uint(sA[rl    ][k0 + tig + 4]);
                a[mt][3] = __float_as_uint(sA[rl + 8][k0 + tig + 4]);
            }
            unsigned bf[2][2];
#pragma unroll
            for (int nt = 0; nt < 2; nt++) {
                int col = wd*16 + nt*8 + gid;
                bf[nt][0] = __float_as_uint(sV[k0 + tig    ][col]);
                bf[nt][1] = __float_as_uint(sV[k0 + tig + 4][col]);
            }
#pragma unroll
            for (int mt = 0; mt < 2; mt++)
#pragma unroll
                for (int nt = 0; nt < 2; nt++)
                    mma_tf32(c[mt][nt], a[mt][0], a[mt][1], a[mt][2], a[mt][3],
                             bf[nt][0], bf[nt][1]);
        }
    }

    // epilogue: normalizer = q' . ks_sum ; divide and store (float2 per C pair)
#pragma unroll
    for (int mt = 0; mt < 2; mt++) {
        int i_lo = wi*32 + mt*16 + gid;
        int i_hi = i_lo + 8;
        float slo = 0.f, shi = 0.f;
#pragma unroll
        for (int m = 0; m < 8; m++) {
            slo += sQ[m][i_lo] * sKS[m];
            shi += sQ[m][i_hi] * sKS[m];
        }
        float inv_lo = 1.f / slo, inv_hi = 1.f / shi;
#pragma unroll
        for (int nt = 0; nt < 2; nt++) {
            int d0 = wd*16 + nt*8 + 2*tig;
            float2 olo = make_float2(c[mt][nt][0]*inv_lo, c[mt][nt][1]*inv_lo);
            float2 ohi = make_float2(c[mt][nt][2]*inv_hi, c[mt][nt][3]*inv_hi);
            *(float2*)&out[(((size_t)(b*Lseq + i0 + i_lo))*Hh + h)*Dh + d0] = olo;
            *(float2*)&out[(((size_t)(b*Lseq + i0 + i_hi))*Hh + h)*Dh + d0] = ohi;
        }
    }
}

// ---------------------------------------------------------------------------
extern "C" void kernel_launch(void* const* d_in, const int* in_sizes, int n_in,
                              void* d_out, int out_size) {
    const float* q    = (const float*)d_in[0];
    const float* k    = (const float*)d_in[1];
    const float* v    = (const float*)d_in[2];
    const float* proj = (const float*)d_in[3];
    const float* mask = (const float*)d_in[4];
    float* out = (float*)d_out;

    featurize_kernel<<<dim3(ROWS/32, 2), 256>>>(q, k, proj);
    colsum_init_kernel<<<(Hh*Lseq + 255)/256, 256>>>();
    colsum_kernel<<<dim3(Hh, 4), 576>>>(mask);
    kssum_kernel<<<Bsz*Hh, 256>>>();
    attn_main_kernel<<<dim3(Lseq/64, Hh, Bsz), 256>>>(v, mask, out);
}

// round 8
// speedup vs baseline: 1.9780x; 1.2407x over previous
#include <cuda_runtime.h>

#define Bsz 16
#define Lseq 576
#define Hh 12
#define Dh 64
#define Mf 8
#define ROWS (Bsz*Lseq*Hh)   // 110592
#define NJT (Lseq/64)        // 9

// Scratch (device globals: allocation-free rule)
__device__ float g_qp[Bsz*Hh*Lseq*Mf];     // [B][H][L][M]
__device__ float g_kp[Bsz*Hh*Lseq*Mf];     // [B][H][L][M]
__device__ float g_colsum[Hh*Lseq];        // [H][L]
__device__ float g_kssum[Bsz*Hh*Mf];       // [B][H][M]

__device__ __forceinline__ float to_tf32(float x) {
    float r;
    asm("cvt.rna.tf32.f32 %0, %1;" : "=f"(r) : "f"(x));
    return r;
}

__device__ __forceinline__ void mma_tf32(float c[4],
                                         unsigned a0, unsigned a1, unsigned a2, unsigned a3,
                                         unsigned b0, unsigned b1) {
    asm volatile(
        "mma.sync.aligned.m16n8k8.row.col.f32.tf32.tf32.f32 "
        "{%0,%1,%2,%3}, {%4,%5,%6,%7}, {%8,%9}, {%0,%1,%2,%3};\n"
        : "+f"(c[0]), "+f"(c[1]), "+f"(c[2]), "+f"(c[3])
        : "r"(a0), "r"(a1), "r"(a2), "r"(a3), "r"(b0), "r"(b1));
}

// ---------------------------------------------------------------------------
// Kernel 1: q' / k' = relu(ratio * x @ projT) + 1e-3, written [B][H][L][M]
// ---------------------------------------------------------------------------
__global__ void featurize_kernel(const float* __restrict__ q,
                                 const float* __restrict__ k,
                                 const float* __restrict__ proj) {
    const float* x = (blockIdx.y == 0) ? q : k;
    float* outp    = (blockIdx.y == 0) ? g_qp : g_kp;

    __shared__ __align__(16) float sX[32][68];
    __shared__ __align__(16) float sP[8][68];

    int t = threadIdx.x;
    for (int idx = t; idx < Mf*Dh; idx += 256)
        sP[idx >> 6][idx & 63] = proj[idx];

    int row0 = blockIdx.x * 32;
    for (int idx = t; idx < 32*Dh; idx += 256)
        sX[idx >> 6][idx & 63] = x[(size_t)row0 * Dh + idx];
    __syncthreads();

    int r = t >> 3, m = t & 7;
    const float4* xr = (const float4*)&sX[r][0];
    const float4* pr = (const float4*)&sP[m][0];
    float acc = 0.f;
#pragma unroll
    for (int dd = 0; dd < Dh/4; dd++) {
        float4 xv = xr[dd], pv = pr[dd];
        acc += xv.x*pv.x + xv.y*pv.y + xv.z*pv.z + xv.w*pv.w;
    }
    const float ratio = 0.35355339059327373f;   // 1/sqrt(8)
    float res = fmaxf(acc * ratio, 0.f) + 1e-3f;

    int row = row0 + r;                 // row = (b*L + l)*H + h
    int h  = row % Hh;
    int bl = row / Hh;
    int l  = bl % Lseq;
    int b  = bl / Lseq;
    outp[(((size_t)(b*Hh + h))*Lseq + l)*Mf + m] = res;
}

// ---------------------------------------------------------------------------
// Kernel 2: zero g_colsum and g_kssum
// ---------------------------------------------------------------------------
__global__ void zero_init_kernel() {
    int i = blockIdx.x * 256 + threadIdx.x;
    if (i < Hh*Lseq) g_colsum[i] = 0.f;
    if (i < Bsz*Hh*Mf) g_kssum[i] = 0.f;
}

// colsum[h][j] = sum_i mask[h][i][j]; grid (Hh, 16), 36 i-rows per block
__global__ void colsum_kernel(const float* __restrict__ mask) {
    int h = blockIdx.x;
    int chunk = blockIdx.y;
    int j = threadIdx.x;
    int i0 = chunk * 36;
    const float* mcol = mask + ((size_t)h*Lseq + i0)*Lseq + j;
    float acc = 0.f;
    for (int i = 0; i < 36; i++) acc += mcol[(size_t)i * Lseq];
    atomicAdd(&g_colsum[h*Lseq + j], acc);
}

// ---------------------------------------------------------------------------
// Kernel 3: ks_sum[b][h][m] = sum_j colsum[h][j] * k'[b][h][j][m]
// grid (Bsz*Hh, 4): each block handles 36 of 144 32-elem chunks; atomicAdd out.
// ---------------------------------------------------------------------------
__global__ void kssum_kernel() {
    int bh = blockIdx.x;             // b*Hh + h
    int h  = bh % Hh;
    int chunk = blockIdx.y;
    int t = threadIdx.x, lane = t & 31, w = t >> 5;   // 8 warps
    const float* kp = g_kp + (size_t)bh * Lseq * Mf;
    const float* cs = g_colsum + h * Lseq;

    float acc = 0.f;
    for (int c = chunk*36 + w; c < chunk*36 + 36; c += 8) {
        int base = c * 32;
        int j = (base + lane) >> 3;          // element index / 8
        acc += kp[base + lane] * cs[j];
    }
    acc += __shfl_down_sync(0xffffffffu, acc, 16);
    acc += __shfl_down_sync(0xffffffffu, acc, 8);

    __shared__ float red[8][8];
    if (lane < 8) red[w][lane] = acc;
    __syncthreads();
    if (t < 8) {
        float s = red[0][t] + red[1][t] + red[2][t] + red[3][t]
                + red[4][t] + red[5][t] + red[6][t] + red[7][t];
        atomicAdd(&g_kssum[bh * Mf + t], s);
    }
}

// ---------------------------------------------------------------------------
// Kernel 4 (main): all-MMA, ping-pong smem pipeline.
//   phase A (mma tf32, K=8): S = Q'K'^T; sA = tf32(mask * S)
//   phase B (mma tf32):      C += sA @ sV
//   epilogue: out = C / (q' . ks_sum)
// Dynamic smem layout (floats):
//   sV [2][64][72] @0, sK [2][8][72] @9216, sA [64][68] @10368,
//   sQ [8][64] @14720, sKS[8] @15232.  total 15240 fl = 60960 B
// ---------------------------------------------------------------------------
#define SM_SV  0
#define SM_SK  9216
#define SM_SA  10368
#define SM_SQ  14720
#define SM_SKS 15232
#define SM_BYTES (15240*4)

__global__ __launch_bounds__(256)
void attn_main_kernel(const float* __restrict__ v,
                      const float* __restrict__ mask,
                      float* __restrict__ out) {
    extern __shared__ float sm[];
    float* sV  = sm + SM_SV;     // [2][64*72]
    float* sK  = sm + SM_SK;     // [2][8*72]
    float* sA  = sm + SM_SA;     // [64*68]
    float* sQ  = sm + SM_SQ;     // [8*64]
    float* sKS = sm + SM_SKS;    // [8]

    int b = blockIdx.z, h = blockIdx.y;
    int i0 = blockIdx.x * 64;
    int t = threadIdx.x;

    const float* qp  = g_qp + (((size_t)(b*Hh + h))*Lseq + i0)*Mf;
    const float* kpb = g_kp + ((size_t)(b*Hh + h))*Lseq*Mf;

    for (int idx = t; idx < 512; idx += 256) sQ[(idx & 7)*64 + (idx >> 3)] = qp[idx];
    if (t < 8) sKS[t] = g_kssum[(b*Hh + h)*Mf + t];

    int lane = t & 31, w = t >> 5;
    int wi = w >> 2, wj = w & 3;          // wj doubles as d-block in phase B
    int gid = lane >> 2, tig = lane & 3;
    int kk = t >> 4, d4 = t & 15;         // V load mapping

    // ---- prologue: tile 0 direct to buf0; tile 1 into regs ----
    float kreg[2];
    float4 vreg[4];
    {   // tile 0
#pragma unroll
        for (int u = 0; u < 2; u++) {
            int idx = t + 256*u;
            sK[(idx & 7)*72 + (idx >> 3)] = kpb[idx];
        }
#pragma unroll
        for (int rr = 0; rr < 4; rr++) {
            int krow = kk + rr*16;
            float4 vv = *(const float4*)&v[(((size_t)(b*Lseq + krow))*Hh + h)*Dh + d4*4];
            vv.x = to_tf32(vv.x); vv.y = to_tf32(vv.y);
            vv.z = to_tf32(vv.z); vv.w = to_tf32(vv.w);
            *(float4*)&sV[krow*72 + d4*4] = vv;
        }
    }
    {   // tile 1 -> regs
#pragma unroll
        for (int u = 0; u < 2; u++) kreg[u] = kpb[64*Mf + t + 256*u];
#pragma unroll
        for (int rr = 0; rr < 4; rr++) {
            int krow = kk + rr*16;
            vreg[rr] = *(const float4*)&v[(((size_t)(b*Lseq + 64 + krow))*Hh + h)*Dh + d4*4];
        }
    }
    __syncthreads();

    // ---- hoist Q' A-fragments (j-invariant) ----
    unsigned aq[2][4];
#pragma unroll
    for (int mt = 0; mt < 2; mt++) {
        int I = wi*32 + mt*16;
        aq[mt][0] = __float_as_uint(to_tf32(sQ[ tig   *64 + I + gid    ]));
        aq[mt][1] = __float_as_uint(to_tf32(sQ[ tig   *64 + I + gid + 8]));
        aq[mt][2] = __float_as_uint(to_tf32(sQ[(tig+4)*64 + I + gid    ]));
        aq[mt][3] = __float_as_uint(to_tf32(sQ[(tig+4)*64 + I + gid + 8]));
    }

    float c[2][2][4];
#pragma unroll
    for (int mt = 0; mt < 2; mt++)
#pragma unroll
        for (int nt = 0; nt < 2; nt++)
#pragma unroll
            for (int u = 0; u < 4; u++) c[mt][nt][u] = 0.f;

    for (int jt = 0; jt < NJT; jt++) {
        int j0 = jt * 64;
        int cur = jt & 1;
        float* sVc = sV + cur*4608;
        float* sKc = sK + cur*576;

        // ---- phase A: S = Q'K'^T (mma), mask multiply, STS sA ----
        const float* mbase = mask + ((size_t)h*Lseq + i0)*Lseq + j0;
#pragma unroll
        for (int nt = 0; nt < 2; nt++) {
            int J = wj*16 + nt*8;
            unsigned b0 = __float_as_uint(to_tf32(sKc[ tig   *72 + J + gid]));
            unsigned b1 = __float_as_uint(to_tf32(sKc[(tig+4)*72 + J + gid]));
#pragma unroll
            for (int mt = 0; mt < 2; mt++) {
                float s[4] = {0.f, 0.f, 0.f, 0.f};
                mma_tf32(s, aq[mt][0], aq[mt][1], aq[mt][2], aq[mt][3], b0, b1);
                int I = wi*32 + mt*16;
                float2 m0 = *(const float2*)&mbase[(size_t)(I + gid    )*Lseq + J + 2*tig];
                float2 m1 = *(const float2*)&mbase[(size_t)(I + gid + 8)*Lseq + J + 2*tig];
                float2 lo = make_float2(to_tf32(s[0]*m0.x), to_tf32(s[1]*m0.y));
                float2 hi = make_float2(to_tf32(s[2]*m1.x), to_tf32(s[3]*m1.y));
                *(float2*)&sA[(I + gid    )*68 + J + 2*tig] = lo;
                *(float2*)&sA[(I + gid + 8)*68 + J + 2*tig] = hi;
            }
        }

        // ---- stage next tile (regs -> other buffer) ----
        if (jt < NJT-1) {
            int nxt = cur ^ 1;
            float* sVn = sV + nxt*4608;
            float* sKn = sK + nxt*576;
#pragma unroll
            for (int u = 0; u < 2; u++) {
                int idx = t + 256*u;
                sKn[(idx & 7)*72 + (idx >> 3)] = kreg[u];
            }
#pragma unroll
            for (int rr = 0; rr < 4; rr++) {
                float4 vv = vreg[rr];
                vv.x = to_tf32(vv.x); vv.y = to_tf32(vv.y);
                vv.z = to_tf32(vv.z); vv.w = to_tf32(vv.w);
                *(float4*)&sVn[(kk + rr*16)*72 + d4*4] = vv;
            }
        }
        __syncthreads();   // sA visible; next-tile stores visible for next iter

        // ---- phase B: C += sA @ sV ----
#pragma unroll
        for (int k0 = 0; k0 < 64; k0 += 8) {
            unsigned a[2][4];
#pragma unroll
            for (int mt = 0; mt < 2; mt++) {
                int rl = wi*32 + mt*16 + gid;
                a[mt][0] = __float_as_uint(sA[(rl    )*68 + k0 + tig    ]);
                a[mt][1] = __float_as_uint(sA[(rl + 8)*68 + k0 + tig    ]);
                a[mt][2] = __float_as_uint(sA[(rl    )*68 + k0 + tig + 4]);
                a[mt][3] = __float_as_uint(sA[(rl + 8)*68 + k0 + tig + 4]);
            }
            unsigned bf[2][2];
#pragma unroll
            for (int nt = 0; nt < 2; nt++) {
                int col = wj*16 + nt*8 + gid;
                bf[nt][0] = __float_as_uint(sVc[(k0 + tig    )*72 + col]);
                bf[nt][1] = __float_as_uint(sVc[(k0 + tig + 4)*72 + col]);
            }
#pragma unroll
            for (int mt = 0; mt < 2; mt++)
#pragma unroll
                for (int nt = 0; nt < 2; nt++)
                    mma_tf32(c[mt][nt], a[mt][0], a[mt][1], a[mt][2], a[mt][3],
                             bf[nt][0], bf[nt][1]);
        }

        // ---- prefetch tile jt+2 into regs ----
        if (jt + 2 < NJT) {
            int j2 = (jt + 2) * 64;
#pragma unroll
            for (int u = 0; u < 2; u++) kreg[u] = kpb[j2*Mf + t + 256*u];
#pragma unroll
            for (int rr = 0; rr < 4; rr++) {
                int krow = kk + rr*16;
                vreg[rr] = *(const float4*)&v[(((size_t)(b*Lseq + j2 + krow))*Hh + h)*Dh + d4*4];
            }
        }
        __syncthreads();   // phase B done: next iter may overwrite sA / buf[cur]
    }

    // ---- epilogue: normalizer = q'.ks_sum; divide; store ----
#pragma unroll
    for (int mt = 0; mt < 2; mt++) {
        int i_lo = wi*32 + mt*16 + gid;
        int i_hi = i_lo + 8;
        float slo = 0.f, shi = 0.f;
#pragma unroll
        for (int m = 0; m < 8; m++) {
            slo += sQ[m*64 + i_lo] * sKS[m];
            shi += sQ[m*64 + i_hi] * sKS[m];
        }
        float inv_lo = 1.f / slo, inv_hi = 1.f / shi;
#pragma unroll
        for (int nt = 0; nt < 2; nt++) {
            int d0 = wj*16 + nt*8 + 2*tig;
            float2 olo = make_float2(c[mt][nt][0]*inv_lo, c[mt][nt][1]*inv_lo);
            float2 ohi = make_float2(c[mt][nt][2]*inv_hi, c[mt][nt][3]*inv_hi);
            *(float2*)&out[(((size_t)(b*Lseq + i0 + i_lo))*Hh + h)*Dh + d0] = olo;
            *(float2*)&out[(((size_t)(b*Lseq + i0 + i_hi))*Hh + h)*Dh + d0] = ohi;
        }
    }
}

// ---------------------------------------------------------------------------
extern "C" void kernel_launch(void* const* d_in, const int* in_sizes, int n_in,
                              void* d_out, int out_size) {
    const float* q    = (const float*)d_in[0];
    const float* k    = (const float*)d_in[1];
    const float* v    = (const float*)d_in[2];
    const float* proj = (const float*)d_in[3];
    const float* mask = (const float*)d_in[4];
    float* out = (float*)d_out;

    cudaFuncSetAttribute(attn_main_kernel,
                         cudaFuncAttributeMaxDynamicSharedMemorySize, SM_BYTES);

    featurize_kernel<<<dim3(ROWS/32, 2), 256>>>(q, k, proj);
    zero_init_kernel<<<(Hh*Lseq + 255)/256, 256>>>();
    colsum_kernel<<<dim3(Hh, 16), 576>>>(mask);
    kssum_kernel<<<dim3(Bsz*Hh, 4), 256>>>();
    attn_main_kernel<<<dim3(Lseq/64, Hh, Bsz), 256, SM_BYTES>>>(v, mask, out);
}

// round 12
// speedup vs baseline: 1.9947x; 1.0084x over previous
#include <cuda_runtime.h>

#define Bsz 16
#define Lseq 576
#define Hh 12
#define Dh 64
#define Mf 8
#define ROWS (Bsz*Lseq*Hh)   // 110592
#define NJT (Lseq/64)        // 9

// Scratch (device globals: allocation-free rule)
__device__ float g_qp[Bsz*Hh*Lseq*Mf];     // [B][H][L][M]
__device__ float g_kp[Bsz*Hh*Lseq*Mf];     // [B][H][L][M]
__device__ float g_colsum[Hh*Lseq];        // [H][L]
__device__ float g_kssum[Bsz*Hh*Mf];       // [B][H][M]

__device__ __forceinline__ float to_tf32(float x) {
    float r;
    asm("cvt.rna.tf32.f32 %0, %1;" : "=f"(r) : "f"(x));
    return r;
}

__device__ __forceinline__ void mma_tf32(float c[4],
                                         unsigned a0, unsigned a1, unsigned a2, unsigned a3,
                                         unsigned b0, unsigned b1) {
    asm volatile(
        "mma.sync.aligned.m16n8k8.row.col.f32.tf32.tf32.f32 "
        "{%0,%1,%2,%3}, {%4,%5,%6,%7}, {%8,%9}, {%0,%1,%2,%3};\n"
        : "+f"(c[0]), "+f"(c[1]), "+f"(c[2]), "+f"(c[3])
        : "r"(a0), "r"(a1), "r"(a2), "r"(a3), "r"(b0), "r"(b1));
}

__device__ __forceinline__ unsigned smem_u32(const void* p) {
    return (unsigned)__cvta_generic_to_shared(p);
}
__device__ __forceinline__ void cp_async16(unsigned dst, const void* src) {
    asm volatile("cp.async.ca.shared.global [%0], [%1], 16;\n" :: "r"(dst), "l"(src));
}
__device__ __forceinline__ void cp_async_commit() {
    asm volatile("cp.async.commit_group;\n");
}
__device__ __forceinline__ void cp_async_wait_all() {
    asm volatile("cp.async.wait_group 0;\n");
}

// ---------------------------------------------------------------------------
// Kernel 1: q' / k' = relu(ratio * x @ projT) + 1e-3, written [B][H][L][M]
// ---------------------------------------------------------------------------
__global__ void featurize_kernel(const float* __restrict__ q,
                                 const float* __restrict__ k,
                                 const float* __restrict__ proj) {
    const float* x = (blockIdx.y == 0) ? q : k;
    float* outp    = (blockIdx.y == 0) ? g_qp : g_kp;

    __shared__ __align__(16) float sX[32][68];
    __shared__ __align__(16) float sP[8][68];

    int t = threadIdx.x;
    for (int idx = t; idx < Mf*Dh; idx += 256)
        sP[idx >> 6][idx & 63] = proj[idx];

    int row0 = blockIdx.x * 32;
    for (int idx = t; idx < 32*Dh; idx += 256)
        sX[idx >> 6][idx & 63] = x[(size_t)row0 * Dh + idx];
    __syncthreads();

    int r = t >> 3, m = t & 7;
    const float4* xr = (const float4*)&sX[r][0];
    const float4* pr = (const float4*)&sP[m][0];
    float acc = 0.f;
#pragma unroll
    for (int dd = 0; dd < Dh/4; dd++) {
        float4 xv = xr[dd], pv = pr[dd];
        acc += xv.x*pv.x + xv.y*pv.y + xv.z*pv.z + xv.w*pv.w;
    }
    const float ratio = 0.35355339059327373f;   // 1/sqrt(8)
    float res = fmaxf(acc * ratio, 0.f) + 1e-3f;

    int row = row0 + r;                 // row = (b*L + l)*H + h
    int h  = row % Hh;
    int bl = row / Hh;
    int l  = bl % Lseq;
    int b  = bl / Lseq;
    outp[(((size_t)(b*Hh + h))*Lseq + l)*Mf + m] = res;
}

// ---------------------------------------------------------------------------
// Kernel 2: zero g_colsum and g_kssum
// ---------------------------------------------------------------------------
__global__ void zero_init_kernel() {
    int i = blockIdx.x * 256 + threadIdx.x;
    if (i < Hh*Lseq) g_colsum[i] = 0.f;
    if (i < Bsz*Hh*Mf) g_kssum[i] = 0.f;
}

// colsum[h][j] = sum_i mask[h][i][j]; grid (Hh, 16), 36 i-rows per block
__global__ void colsum_kernel(const float* __restrict__ mask) {
    int h = blockIdx.x;
    int chunk = blockIdx.y;
    int j = threadIdx.x;
    int i0 = chunk * 36;
    const float* mcol = mask + ((size_t)h*Lseq + i0)*Lseq + j;
    float acc = 0.f;
    for (int i = 0; i < 36; i++) acc += mcol[(size_t)i * Lseq];
    atomicAdd(&g_colsum[h*Lseq + j], acc);
}

// ---------------------------------------------------------------------------
// Kernel 3: ks_sum[b][h][m] = sum_j colsum[h][j] * k'[b][h][j][m]
// ---------------------------------------------------------------------------
__global__ void kssum_kernel() {
    int bh = blockIdx.x;             // b*Hh + h
    int h  = bh % Hh;
    int chunk = blockIdx.y;
    int t = threadIdx.x, lane = t & 31, w = t >> 5;   // 8 warps
    const float* kp = g_kp + (size_t)bh * Lseq * Mf;
    const float* cs = g_colsum + h * Lseq;

    float acc = 0.f;
    for (int c = chunk*36 + w; c < chunk*36 + 36; c += 8) {
        int base = c * 32;
        int j = (base + lane) >> 3;          // element index / 8
        acc += kp[base + lane] * cs[j];
    }
    acc += __shfl_down_sync(0xffffffffu, acc, 16);
    acc += __shfl_down_sync(0xffffffffu, acc, 8);

    __shared__ float red[8][8];
    if (lane < 8) red[w][lane] = acc;
    __syncthreads();
    if (t < 8) {
        float s = red[0][t] + red[1][t] + red[2][t] + red[3][t]
                + red[4][t] + red[5][t] + red[6][t] + red[7][t];
        atomicAdd(&g_kssum[bh * Mf + t], s);
    }
}

// ---------------------------------------------------------------------------
// Kernel 4 (main): all-MMA; ping-pong k'/V; cp.async double-buffered mask.
//   phase A (mma tf32, K=8): S = Q'K'^T; sA = tf32(smemMask * S)
//   phase B (mma tf32):      C += sA @ sV
// Dynamic smem (floats):
//   sV [2][64*72] @0, sK [2][8*72] @9216, sA [64*68] @10368,
//   sQ [8*64] @14720, sKS[8] @15232, sM [2][64*68] @15240
//   total 23944 fl = 95776 B  (2 CTAs/SM)
// ---------------------------------------------------------------------------
#define SM_SV  0
#define SM_SK  9216
#define SM_SA  10368
#define SM_SQ  14720
#define SM_SKS 15232
#define SM_SM  15240
#define SM_BYTES (23944*4)

__global__ __launch_bounds__(256)
void attn_main_kernel(const float* __restrict__ v,
                      const float* __restrict__ mask,
                      float* __restrict__ out) {
    extern __shared__ float sm[];
    float* sV  = sm + SM_SV;     // [2][64*72]
    float* sK  = sm + SM_SK;     // [2][8*72]
    float* sA  = sm + SM_SA;     // [64*68]
    float* sQ  = sm + SM_SQ;     // [8*64]
    float* sKS = sm + SM_SKS;    // [8]
    float* sM  = sm + SM_SM;     // [2][64*68]

    int b = blockIdx.z, h = blockIdx.y;
    int i0 = blockIdx.x * 64;
    int t = threadIdx.x;

    const float* qp  = g_qp + (((size_t)(b*Hh + h))*Lseq + i0)*Mf;
    const float* kpb = g_kp + ((size_t)(b*Hh + h))*Lseq*Mf;
    const float* mtile = mask + ((size_t)h*Lseq + i0)*Lseq;   // row i, col j abs

    // ---- mask tile 0 -> sM[0] via cp.async (issued first for max overlap) ----
    {
        // 64 rows x 16 chunks of 16B; 4 chunks per thread
#pragma unroll
        for (int u = 0; u < 4; u++) {
            int ch = t + 256*u;
            int row = ch >> 4, c16 = ch & 15;
            cp_async16(smem_u32(&sM[row*68 + c16*4]), &mtile[(size_t)row*Lseq + c16*4]);
        }
        cp_async_commit();
    }

    for (int idx = t; idx < 512; idx += 256) sQ[(idx & 7)*64 + (idx >> 3)] = qp[idx];
    if (t < 8) sKS[t] = g_kssum[(b*Hh + h)*Mf + t];

    int lane = t & 31, w = t >> 5;
    int wi = w >> 2, wj = w & 3;
    int gid = lane >> 2, tig = lane & 3;
    int kk = t >> 4, d4 = t & 15;         // V load mapping

    // ---- prologue: k'/V tile 0 to buf0; tile 1 into regs ----
    float kreg[2];
    float4 vreg[4];
    {
#pragma unroll
        for (int u = 0; u < 2; u++) {
            int idx = t + 256*u;
            sK[(idx & 7)*72 + (idx >> 3)] = kpb[idx];
        }
#pragma unroll
        for (int rr = 0; rr < 4; rr++) {
            int krow = kk + rr*16;
            float4 vv = *(const float4*)&v[(((size_t)(b*Lseq + krow))*Hh + h)*Dh + d4*4];
            vv.x = to_tf32(vv.x); vv.y = to_tf32(vv.y);
            vv.z = to_tf32(vv.z); vv.w = to_tf32(vv.w);
            *(float4*)&sV[krow*72 + d4*4] = vv;
        }
    }
    {
#pragma unroll
        for (int u = 0; u < 2; u++) kreg[u] = kpb[64*Mf + t + 256*u];
#pragma unroll
        for (int rr = 0; rr < 4; rr++) {
            int krow = kk + rr*16;
            vreg[rr] = *(const float4*)&v[(((size_t)(b*Lseq + 64 + krow))*Hh + h)*Dh + d4*4];
        }
    }
    cp_async_wait_all();
    __syncthreads();

    // ---- hoist Q' A-fragments (j-invariant) ----
    unsigned aq[2][4];
#pragma unroll
    for (int mt = 0; mt < 2; mt++) {
        int I = wi*32 + mt*16;
        aq[mt][0] = __float_as_uint(to_tf32(sQ[ tig   *64 + I + gid    ]));
        aq[mt][1] = __float_as_uint(to_tf32(sQ[ tig   *64 + I + gid + 8]));
        aq[mt][2] = __float_as_uint(to_tf32(sQ[(tig+4)*64 + I + gid    ]));
        aq[mt][3] = __float_as_uint(to_tf32(sQ[(tig+4)*64 + I + gid + 8]));
    }

    float c[2][2][4];
#pragma unroll
    for (int mt = 0; mt < 2; mt++)
#pragma unroll
        for (int nt = 0; nt < 2; nt++)
#pragma unroll
            for (int u = 0; u < 4; u++) c[mt][nt][u] = 0.f;

    for (int jt = 0; jt < NJT; jt++) {
        int cur = jt & 1;
        float* sVc = sV + cur*4608;
        float* sKc = sK + cur*576;
        float* sMc = sM + cur*4352;

        // ---- phase A: S = Q'K'^T (mma); multiply by smem mask; STS sA ----
#pragma unroll
        for (int nt = 0; nt < 2; nt++) {
            int J = wj*16 + nt*8;
            unsigned b0 = __float_as_uint(to_tf32(sKc[ tig   *72 + J + gid]));
            unsigned b1 = __float_as_uint(to_tf32(sKc[(tig+4)*72 + J + gid]));
#pragma unroll
            for (int mt = 0; mt < 2; mt++) {
                float s[4] = {0.f, 0.f, 0.f, 0.f};
                mma_tf32(s, aq[mt][0], aq[mt][1], aq[mt][2], aq[mt][3], b0, b1);
                int I = wi*32 + mt*16;
                float2 m0 = *(const float2*)&sMc[(I + gid    )*68 + J + 2*tig];
                float2 m1 = *(const float2*)&sMc[(I + gid + 8)*68 + J + 2*tig];
                float2 lo = make_float2(to_tf32(s[0]*m0.x), to_tf32(s[1]*m0.y));
                float2 hi = make_float2(to_tf32(s[2]*m1.x), to_tf32(s[3]*m1.y));
                *(float2*)&sA[(I + gid    )*68 + J + 2*tig] = lo;
                *(float2*)&sA[(I + gid + 8)*68 + J + 2*tig] = hi;
            }
        }

        // ---- stage next k'/V tile (regs -> other buffer) ----
        if (jt < NJT-1) {
            int nxt = cur ^ 1;
            float* sVn = sV + nxt*4608;
            float* sKn = sK + nxt*576;
#pragma unroll
            for (int u = 0; u < 2; u++) {
                int idx = t + 256*u;
                sKn[(idx & 7)*72 + (idx >> 3)] = kreg[u];
            }
#pragma unroll
            for (int rr = 0; rr < 4; rr++) {
                float4 vv = vreg[rr];
                vv.x = to_tf32(vv.x); vv.y = to_tf32(vv.y);
                vv.z = to_tf32(vv.z); vv.w = to_tf32(vv.w);
                *(float4*)&sVn[(kk + rr*16)*72 + d4*4] = vv;
            }
            // ---- issue cp.async for mask tile jt+1 into sM[nxt] ----
            float* sMn = sM + nxt*4352;
            const float* msrc = mtile + (size_t)(jt+1)*64;
#pragma unroll
            for (int u = 0; u < 4; u++) {
                int ch = t + 256*u;
                int row = ch >> 4, c16 = ch & 15;
                cp_async16(smem_u32(&sMn[row*68 + c16*4]), &msrc[(size_t)row*Lseq + c16*4]);
            }
            cp_async_commit();
        }
        __syncthreads();   // sA + staged k'/V visible

        // ---- phase B: C += sA @ sV ----
#pragma unroll
        for (int k0 = 0; k0 < 64; k0 += 8) {
            unsigned a[2][4];
#pragma unroll
            for (int mt = 0; mt < 2; mt++) {
                int rl = wi*32 + mt*16 + gid;
                a[mt][0] = __float_as_uint(sA[(rl    )*68 + k0 + tig    ]);
                a[mt][1] = __float_as_uint(sA[(rl + 8)*68 + k0 + tig    ]);
                a[mt][2] = __float_as_uint(sA[(rl    )*68 + k0 + tig + 4]);
                a[mt][3] = __float_as_uint(sA[(rl + 8)*68 + k0 + tig + 4]);
            }
            unsigned bf[2][2];
#pragma unroll
            for (int nt = 0; nt < 2; nt++) {
                int col = wj*16 + nt*8 + gid;
                bf[nt][0] = __float_as_uint(sVc[(k0 + tig    )*72 + col]);
                bf[nt][1] = __float_as_uint(sVc[(k0 + tig + 4)*72 + col]);
            }
#pragma unroll
            for (int mt = 0; mt < 2; mt++)
#pragma unroll
                for (int nt = 0; nt < 2; nt++)
                    mma_tf32(c[mt][nt], a[mt][0], a[mt][1], a[mt][2], a[mt][3],
                             bf[nt][0], bf[nt][1]);
        }

        // ---- prefetch k'/V tile jt+2 into regs ----
        if (jt + 2 < NJT) {
            int j2 = (jt + 2) * 64;
#pragma unroll
            for (int u = 0; u < 2; u++) kreg[u] = kpb[j2*Mf + t + 256*u];
#pragma unroll
            for (int rr = 0; rr < 4; rr++) {
                int krow = kk + rr*16;
                vreg[rr] = *(const float4*)&v[(((size_t)(b*Lseq + j2 + krow))*Hh + h)*Dh + d4*4];
            }
        }
        cp_async_wait_all();   // mask tile jt+1 landed
        __syncthreads();       // visible to all; sA/buf[cur] reusable
    }

    // ---- epilogue: normalizer = q'.ks_sum; divide; store ----
#pragma unroll
    for (int mt = 0; mt < 2; mt++) {
        int i_lo = wi*32 + mt*16 + gid;
        int i_hi = i_lo + 8;
        float slo = 0.f, shi = 0.f;
#pragma unroll
        for (int m = 0; m < 8; m++) {
            slo += sQ[m*64 + i_lo] * sKS[m];
            shi += sQ[m*64 + i_hi] * sKS[m];
        }
        float inv_lo = 1.f / slo, inv_hi = 1.f / shi;
#pragma unroll
        for (int nt = 0; nt < 2; nt++) {
            int d0 = wj*16 + nt*8 + 2*tig;
            float2 olo = make_float2(c[mt][nt][0]*inv_lo, c[mt][nt][1]*inv_lo);
            float2 ohi = make_float2(c[mt][nt][2]*inv_hi, c[mt][nt][3]*inv_hi);
            *(float2*)&out[(((size_t)(b*Lseq + i0 + i_lo))*Hh + h)*Dh + d0] = olo;
            *(float2*)&out[(((size_t)(b*Lseq + i0 + i_hi))*Hh + h)*Dh + d0] = ohi;
        }
    }
}

// ---------------------------------------------------------------------------
extern "C" void kernel_launch(void* const* d_in, const int* in_sizes, int n_in,
                              void* d_out, int out_size) {
    const float* q    = (const float*)d_in[0];
    const float* k    = (const float*)d_in[1];
    const float* v    = (const float*)d_in[2];
    const float* proj = (const float*)d_in[3];
    const float* mask = (const float*)d_in[4];
    float* out = (float*)d_out;

    cudaFuncSetAttribute(attn_main_kernel,
                         cudaFuncAttributeMaxDynamicSharedMemorySize, SM_BYTES);

    featurize_kernel<<<dim3(ROWS/32, 2), 256>>>(q, k, proj);
    zero_init_kernel<<<(Hh*Lseq + 255)/256, 256>>>();
    colsum_kernel<<<dim3(Hh, 16), 576>>>(mask);
    kssum_kernel<<<dim3(Bsz*Hh, 4), 256>>>();
    attn_main_kernel<<<dim3(Lseq/64, Hh, Bsz), 256, SM_BYTES>>>(v, mask, out);
}